// round 3
// baseline (speedup 1.0000x reference)
#include <cuda_runtime.h>
#include <math.h>

#define NUM_B 8192
#define T_LEN 1024
#define HID   64
#define EPSF  1e-6f
#define TILE  16          // steps per tile
#define NTILE (T_LEN / TILE)
#define YP    20          // padded row pitch in words (80B: 16B-aligned, low-conflict)

__device__ float g_l[NUM_B], g_g[NUM_B], g_a[NUM_B], g_c0[NUM_B],
                 g_uf1[NUM_B], g_uf0[NUM_B], g_prior[NUM_B];

// ---------------------------------------------------------------------------
// Kernel 1: embed gather + MLP + sigmoid head. 8 rows/block, 1024 blocks.
// ---------------------------------------------------------------------------
__global__ __launch_bounds__(512) void mlp_kernel(
    const int*   __restrict__ X,
    const float* __restrict__ embed,
    const float* __restrict__ W0, const float* __restrict__ b0,
    const float* __restrict__ W1, const float* __restrict__ b1,
    const float* __restrict__ Wout, const float* __restrict__ bout)
{
    __shared__ float sW0[HID * HID];
    __shared__ float sW1[HID * HID];
    __shared__ float sWo[HID * 4];
    __shared__ float sb0[HID], sb1[HID], sbo[4];
    __shared__ float sh[8][HID];
    __shared__ float sp[8][4];

    const int t = threadIdx.x;
    for (int i = t; i < HID * HID; i += 512) { sW0[i] = W0[i]; sW1[i] = W1[i]; }
    if (t < HID * 4) sWo[t] = Wout[t];
    if (t < HID)    { sb0[t] = b0[t]; sb1[t] = b1[t]; }
    if (t < 4)       sbo[t] = bout[t];

    const int j   = t & 63;
    const int r   = t >> 6;
    const int row = blockIdx.x * 8 + r;

    const int xi = X[row];
    sh[r][j] = embed[(size_t)xi * HID + j];
    __syncthreads();

    float acc = sb0[j];
#pragma unroll
    for (int i = 0; i < HID; i++) acc = fmaf(sh[r][i], sW0[i * HID + j], acc);
    acc = fmaxf(acc, 0.0f);
    __syncthreads();
    sh[r][j] = acc;
    __syncthreads();

    float acc1 = sb1[j];
#pragma unroll
    for (int i = 0; i < HID; i++) acc1 = fmaf(sh[r][i], sW1[i * HID + j], acc1);
    acc1 = fmaxf(acc1, 0.0f);
    __syncthreads();
    sh[r][j] = acc1;
    __syncthreads();

    if (j < 4) {
        float acc2 = sbo[j];
#pragma unroll
        for (int i = 0; i < HID; i++) acc2 = fmaf(sh[r][i], sWo[i * 4 + j], acc2);
        float pv = 1.0f / (1.0f + expf(-acc2));
        pv = fminf(fmaxf(pv, EPSF), 1.0f - EPSF);
        sp[r][j] = pv;
    }
    __syncthreads();

    if (j == 0) {
        const float l  = sp[r][0];
        const float gg = sp[r][1];
        const float s  = sp[r][2];
        const float pr = sp[r][3];
        const float a  = 1.0f - s - gg;
        g_l[row]   = l;
        g_g[row]   = gg;
        g_a[row]   = a;
        g_c0[row]  = 1.0f - gg;
        g_uf1[row] = (1.0f - s) * (1.0f - l);
        g_uf0[row] = s * (1.0f - l);
        g_prior[row] = pr;
    }
}

// ---------------------------------------------------------------------------
// Kernel 2: BKT scan. Block = 64 threads (2 warps, SMSP 0/1), grid = 128.
// y staged in via cp.async (coalesced); outputs staged OUT via smem and
// drained with coalesced STG.128 (4 lanes per row => 8 lines/instr, not 32).
// Chain per step: FFMA(4) -> MUFU.RCP(16) -> FFMA(4) -> FMNMX(4) = 28 cyc.
// ---------------------------------------------------------------------------
__device__ __forceinline__ unsigned smem_u32(const void* p) {
    return (unsigned)__cvta_generic_to_shared(p);
}

__global__ __launch_bounds__(64) void bkt_kernel(
    const int* __restrict__ y, float* __restrict__ out)
{
    __shared__ __align__(16) int   s_y[2][2][32][YP];   // [warp][buf][row][step]
    __shared__ __align__(16) float s_o[2][2][32][YP];   // [warp][plane][row][step]

    const int warp = threadIdx.x >> 5;
    const int lane = threadIdx.x & 31;
    const int rowbase = (blockIdx.x * 2 + warp) * 32;
    const int row = rowbase + lane;

    const float l   = g_l[row];
    const float gg  = g_g[row];
    const float a   = g_a[row];
    const float c0  = g_c0[row];
    const float uf1 = g_uf1[row];
    const float uf0 = g_uf0[row];
    const float na  = -a;
    const float HI  = 1.0f - EPSF;
    float latent    = g_prior[row];

    // cp.async mapping: granule g = lane (per instr), row = g>>2 (+8/instr),
    // 4 lanes x 16B cover one row's 64B tile segment.
    const int lr = lane >> 2;       // row sub-index 0..7
    const int lc = (lane & 3) * 4;  // int offset within tile
    const int* yw = y + (size_t)rowbase * T_LEN;

#define LOAD_TILE(K, B) do {                                                  \
        _Pragma("unroll")                                                     \
        for (int i = 0; i < 4; ++i) {                                         \
            const int rr = 8 * i + lr;                                        \
            const int* src = yw + (size_t)rr * T_LEN + (K) * TILE + lc;       \
            unsigned dst = smem_u32(&s_y[warp][(B)][rr][lc]);                 \
            asm volatile("cp.async.cg.shared.global [%0], [%1], 16;"          \
                         :: "r"(dst), "l"(src));                              \
        }                                                                     \
        asm volatile("cp.async.commit_group;" ::: "memory");                  \
    } while (0)

    LOAD_TILE(0, 0);
    LOAD_TILE(1, 1);

    float* const outc = out + (size_t)rowbase * T_LEN;
    float* const outl = out + (size_t)NUM_B * T_LEN + (size_t)rowbase * T_LEN;

#define STEP(yv, co, lo) do {                                         \
        const bool  p  = (yv) > 0;                                    \
        const float at = p ? a   : na;                                \
        const float ct = p ? gg  : c0;                                \
        const float uf = p ? uf1 : uf0;                               \
        const float den = fmaf(latent, at, ct);                       \
        const float m   = latent * uf;                                \
        float rr_;                                                    \
        asm("rcp.approx.ftz.f32 %0, %1;" : "=f"(rr_) : "f"(den));     \
        (co) = fmaf(latent, a, gg);                                   \
        (lo) = latent;                                                \
        latent = fminf(fmaf(m, rr_, l), HI);                          \
    } while (0)

#pragma unroll 1
    for (int k = 0; k < NTILE; ++k) {
        const int b = k & 1;
        asm volatile("cp.async.wait_group 1;" ::: "memory");
        __syncwarp();

        // ---- scan 16 steps, results to smem staging ----
#pragma unroll
        for (int sub = 0; sub < 4; ++sub) {
            const int4 q = *reinterpret_cast<const int4*>(&s_y[warp][b][lane][sub * 4]);
            float4 cv, lv;
            STEP(q.x, cv.x, lv.x); STEP(q.y, cv.y, lv.y);
            STEP(q.z, cv.z, lv.z); STEP(q.w, cv.w, lv.w);
            *reinterpret_cast<float4*>(&s_o[warp][0][lane][sub * 4]) = cv;
            *reinterpret_cast<float4*>(&s_o[warp][1][lane][sub * 4]) = lv;
        }
        __syncwarp();

        // ---- coalesced drain: 4 lanes per row, rows 8 per instr ----
#pragma unroll
        for (int i = 0; i < 4; ++i) {
            const int rr = 8 * i + lr;
            const float4 vc = *reinterpret_cast<const float4*>(&s_o[warp][0][rr][lc]);
            *reinterpret_cast<float4*>(outc + (size_t)rr * T_LEN + k * TILE + lc) = vc;
            const float4 vl = *reinterpret_cast<const float4*>(&s_o[warp][1][rr][lc]);
            *reinterpret_cast<float4*>(outl + (size_t)rr * T_LEN + k * TILE + lc) = vl;
        }

        __syncwarp();   // all lanes done with s_y[b] before refill
        if (k < NTILE - 2) {
            LOAD_TILE(k + 2, b);
        } else {
            asm volatile("cp.async.commit_group;" ::: "memory");
        }
    }
#undef STEP
#undef LOAD_TILE
}

// ---------------------------------------------------------------------------
extern "C" void kernel_launch(void* const* d_in, const int* in_sizes, int n_in,
                              void* d_out, int out_size)
{
    const int*   X     = (const int*)  d_in[0];
    const int*   y     = (const int*)  d_in[1];
    const float* embed = (const float*)d_in[2];
    const float* W0    = (const float*)d_in[3];
    const float* b0    = (const float*)d_in[4];
    const float* W1    = (const float*)d_in[5];
    const float* b1    = (const float*)d_in[6];
    const float* Wout  = (const float*)d_in[7];
    const float* bout  = (const float*)d_in[8];

    mlp_kernel<<<NUM_B / 8, 512>>>(X, embed, W0, b0, W1, b1, Wout, bout);
    bkt_kernel<<<NUM_B / 64, 64>>>(y, (float*)d_out);
}

// round 4
// speedup vs baseline: 1.0498x; 1.0498x over previous
#include <cuda_runtime.h>
#include <math.h>

#define NUM_B 8192
#define T_LEN 1024
#define HID   64
#define EPSF  1e-6f
#define TILE  16
#define NTILE (T_LEN / TILE)
#define YP    20

// Per-row scan constants (odds-space affine recurrence).
__device__ float g_A0[NUM_B], g_A1[NUM_B], g_B[NUM_B],
                 g_o0[NUM_B], g_s1[NUM_B], g_gg[NUM_B];

// ---------------------------------------------------------------------------
// Kernel 1: embed gather + MLP + sigmoid head + odds-space constants.
// ---------------------------------------------------------------------------
__global__ __launch_bounds__(512) void mlp_kernel(
    const int*   __restrict__ X,
    const float* __restrict__ embed,
    const float* __restrict__ W0, const float* __restrict__ b0,
    const float* __restrict__ W1, const float* __restrict__ b1,
    const float* __restrict__ Wout, const float* __restrict__ bout)
{
    __shared__ float sW0[HID * HID];
    __shared__ float sW1[HID * HID];
    __shared__ float sWo[HID * 4];
    __shared__ float sb0[HID], sb1[HID], sbo[4];
    __shared__ float sh[8][HID];
    __shared__ float sp[8][4];

    const int t = threadIdx.x;
    for (int i = t; i < HID * HID; i += 512) { sW0[i] = W0[i]; sW1[i] = W1[i]; }
    if (t < HID * 4) sWo[t] = Wout[t];
    if (t < HID)    { sb0[t] = b0[t]; sb1[t] = b1[t]; }
    if (t < 4)       sbo[t] = bout[t];

    const int j   = t & 63;
    const int r   = t >> 6;
    const int row = blockIdx.x * 8 + r;

    const int xi = X[row];
    sh[r][j] = embed[(size_t)xi * HID + j];
    __syncthreads();

    float acc = sb0[j];
#pragma unroll
    for (int i = 0; i < HID; i++) acc = fmaf(sh[r][i], sW0[i * HID + j], acc);
    acc = fmaxf(acc, 0.0f);
    __syncthreads();
    sh[r][j] = acc;
    __syncthreads();

    float acc1 = sb1[j];
#pragma unroll
    for (int i = 0; i < HID; i++) acc1 = fmaf(sh[r][i], sW1[i * HID + j], acc1);
    acc1 = fmaxf(acc1, 0.0f);
    __syncthreads();
    sh[r][j] = acc1;
    __syncthreads();

    if (j < 4) {
        float acc2 = sbo[j];
#pragma unroll
        for (int i = 0; i < HID; i++) acc2 = fmaf(sh[r][i], sWo[i * 4 + j], acc2);
        float pv = 1.0f / (1.0f + expf(-acc2));
        pv = fminf(fmaxf(pv, EPSF), 1.0f - EPSF);
        sp[r][j] = pv;
    }
    __syncthreads();

    if (j == 0) {
        const float l  = sp[r][0];
        const float gg = sp[r][1];
        const float s  = sp[r][2];
        const float pr = sp[r][3];
        const float il = 1.0f / (1.0f - l);     // accurate div, once per row
        g_A1[row] = (1.0f - s) / (gg * (1.0f - l));
        g_A0[row] = s / ((1.0f - gg) * (1.0f - l));
        g_B[row]  = l * il;
        g_o0[row] = pr / (1.0f - pr);
        g_s1[row] = 1.0f - s;
        g_gg[row] = gg;
    }
}

// ---------------------------------------------------------------------------
// Kernel 2: BKT scan in ODDS space.
//   chain/step: o = fminf(fmaf(A_y, o, B), OMAX)    (FFMA + FMNMX ~ 9 cyc)
//   off-chain:  inv = rcp(1+o); latent = o*inv; correct = fmaf(o,1-s,g)*inv
// y staged via cp.async; outputs staged via smem, drained coalesced.
// ---------------------------------------------------------------------------
__device__ __forceinline__ unsigned smem_u32(const void* p) {
    return (unsigned)__cvta_generic_to_shared(p);
}

__global__ __launch_bounds__(64) void bkt_kernel(
    const int* __restrict__ y, float* __restrict__ out)
{
    __shared__ __align__(16) int   s_y[2][2][32][YP];
    __shared__ __align__(16) float s_o[2][2][32][YP];

    const int warp = threadIdx.x >> 5;
    const int lane = threadIdx.x & 31;
    const int rowbase = (blockIdx.x * 2 + warp) * 32;
    const int row = rowbase + lane;

    const float A0 = g_A0[row];
    const float A1 = g_A1[row];
    const float Bc = g_B[row];
    const float s1 = g_s1[row];
    const float gg = g_gg[row];
    const float OMAX = (1.0f - EPSF) / EPSF;   // odds(1-eps); lower clip never binds
    float o = g_o0[row];

    const int lr = lane >> 2;
    const int lc = (lane & 3) * 4;
    const int* yw = y + (size_t)rowbase * T_LEN;

#define LOAD_TILE(K, B) do {                                                  \
        _Pragma("unroll")                                                     \
        for (int i = 0; i < 4; ++i) {                                         \
            const int rr = 8 * i + lr;                                        \
            const int* src = yw + (size_t)rr * T_LEN + (K) * TILE + lc;       \
            unsigned dst = smem_u32(&s_y[warp][(B)][rr][lc]);                 \
            asm volatile("cp.async.cg.shared.global [%0], [%1], 16;"          \
                         :: "r"(dst), "l"(src));                              \
        }                                                                     \
        asm volatile("cp.async.commit_group;" ::: "memory");                  \
    } while (0)

    LOAD_TILE(0, 0);
    LOAD_TILE(1, 1);

    float* const outc = out + (size_t)rowbase * T_LEN;
    float* const outl = out + (size_t)NUM_B * T_LEN + (size_t)rowbase * T_LEN;

#define STEP(Av, co, lo) do {                                         \
        float inv_;                                                   \
        asm("rcp.approx.ftz.f32 %0, %1;" : "=f"(inv_) : "f"(1.0f + o)); \
        (lo) = o * inv_;                                              \
        (co) = fmaf(o, s1, gg) * inv_;                                \
        o = fminf(fmaf((Av), o, Bc), OMAX);                           \
    } while (0)

#pragma unroll 1
    for (int k = 0; k < NTILE; ++k) {
        const int b = k & 1;
        asm volatile("cp.async.wait_group 1;" ::: "memory");
        __syncwarp();

#pragma unroll
        for (int sub = 0; sub < 4; ++sub) {
            const int4 q = *reinterpret_cast<const int4*>(&s_y[warp][b][lane][sub * 4]);
            const float Ax = (q.x > 0) ? A1 : A0;
            const float Ay = (q.y > 0) ? A1 : A0;
            const float Az = (q.z > 0) ? A1 : A0;
            const float Aw = (q.w > 0) ? A1 : A0;
            float4 cv, lv;
            STEP(Ax, cv.x, lv.x); STEP(Ay, cv.y, lv.y);
            STEP(Az, cv.z, lv.z); STEP(Aw, cv.w, lv.w);
            *reinterpret_cast<float4*>(&s_o[warp][0][lane][sub * 4]) = cv;
            *reinterpret_cast<float4*>(&s_o[warp][1][lane][sub * 4]) = lv;
        }
        __syncwarp();

#pragma unroll
        for (int i = 0; i < 4; ++i) {
            const int rr = 8 * i + lr;
            const float4 vc = *reinterpret_cast<const float4*>(&s_o[warp][0][rr][lc]);
            *reinterpret_cast<float4*>(outc + (size_t)rr * T_LEN + k * TILE + lc) = vc;
            const float4 vl = *reinterpret_cast<const float4*>(&s_o[warp][1][rr][lc]);
            *reinterpret_cast<float4*>(outl + (size_t)rr * T_LEN + k * TILE + lc) = vl;
        }

        __syncwarp();
        if (k < NTILE - 2) {
            LOAD_TILE(k + 2, b);
        } else {
            asm volatile("cp.async.commit_group;" ::: "memory");
        }
    }
#undef STEP
#undef LOAD_TILE
}

// ---------------------------------------------------------------------------
extern "C" void kernel_launch(void* const* d_in, const int* in_sizes, int n_in,
                              void* d_out, int out_size)
{
    const int*   X     = (const int*)  d_in[0];
    const int*   y     = (const int*)  d_in[1];
    const float* embed = (const float*)d_in[2];
    const float* W0    = (const float*)d_in[3];
    const float* b0    = (const float*)d_in[4];
    const float* W1    = (const float*)d_in[5];
    const float* b1    = (const float*)d_in[6];
    const float* Wout  = (const float*)d_in[7];
    const float* bout  = (const float*)d_in[8];

    mlp_kernel<<<NUM_B / 8, 512>>>(X, embed, W0, b0, W1, b1, Wout, bout);
    bkt_kernel<<<NUM_B / 64, 64>>>(y, (float*)d_out);
}

// round 5
// speedup vs baseline: 1.4062x; 1.3394x over previous
#include <cuda_runtime.h>
#include <math.h>

#define NUM_B 8192
#define T_LEN 1024
#define HID   64
#define EPSF  1e-6f
#define TILE  16
#define NTILE (T_LEN / TILE)
#define YP    20

// Per-row scan constants (odds-space affine recurrence).
__device__ float g_A0[NUM_B], g_A1[NUM_B], g_B[NUM_B],
                 g_o0[NUM_B], g_s1[NUM_B], g_gg[NUM_B];

// ---------------------------------------------------------------------------
// Kernel 1: embed gather + MLP + sigmoid head + odds-space constants.
// ---------------------------------------------------------------------------
__global__ __launch_bounds__(512) void mlp_kernel(
    const int*   __restrict__ X,
    const float* __restrict__ embed,
    const float* __restrict__ W0, const float* __restrict__ b0,
    const float* __restrict__ W1, const float* __restrict__ b1,
    const float* __restrict__ Wout, const float* __restrict__ bout)
{
    __shared__ float sW0[HID * HID];
    __shared__ float sW1[HID * HID];
    __shared__ float sWo[HID * 4];
    __shared__ float sb0[HID], sb1[HID], sbo[4];
    __shared__ float sh[8][HID];
    __shared__ float sp[8][4];

    const int t = threadIdx.x;
    for (int i = t; i < HID * HID; i += 512) { sW0[i] = W0[i]; sW1[i] = W1[i]; }
    if (t < HID * 4) sWo[t] = Wout[t];
    if (t < HID)    { sb0[t] = b0[t]; sb1[t] = b1[t]; }
    if (t < 4)       sbo[t] = bout[t];

    const int j   = t & 63;
    const int r   = t >> 6;
    const int row = blockIdx.x * 8 + r;

    const int xi = X[row];
    sh[r][j] = embed[(size_t)xi * HID + j];
    __syncthreads();

    float acc = sb0[j];
#pragma unroll
    for (int i = 0; i < HID; i++) acc = fmaf(sh[r][i], sW0[i * HID + j], acc);
    acc = fmaxf(acc, 0.0f);
    __syncthreads();
    sh[r][j] = acc;
    __syncthreads();

    float acc1 = sb1[j];
#pragma unroll
    for (int i = 0; i < HID; i++) acc1 = fmaf(sh[r][i], sW1[i * HID + j], acc1);
    acc1 = fmaxf(acc1, 0.0f);
    __syncthreads();
    sh[r][j] = acc1;
    __syncthreads();

    if (j < 4) {
        float acc2 = sbo[j];
#pragma unroll
        for (int i = 0; i < HID; i++) acc2 = fmaf(sh[r][i], sWo[i * 4 + j], acc2);
        float pv = 1.0f / (1.0f + expf(-acc2));
        pv = fminf(fmaxf(pv, EPSF), 1.0f - EPSF);
        sp[r][j] = pv;
    }
    __syncthreads();

    if (j == 0) {
        const float l  = sp[r][0];
        const float gg = sp[r][1];
        const float s  = sp[r][2];
        const float pr = sp[r][3];
        const float il = 1.0f / (1.0f - l);
        g_A1[row] = (1.0f - s) / (gg * (1.0f - l));
        g_A0[row] = s / ((1.0f - gg) * (1.0f - l));
        g_B[row]  = l * il;
        g_o0[row] = pr / (1.0f - pr);
        g_s1[row] = 1.0f - s;
        g_gg[row] = gg;
    }
}

// ---------------------------------------------------------------------------
// Kernel 2: BKT scan in odds space, phase-separated per 16-step tile:
//   A: build likelihood-ratio selects A[16] (off-chain)
//   B: pure chain  o_{i+1} = min(fma(A[i], o_i, B), OMAX)   (FFMA+FMNMX)
//   C: outputs     inv=rcp(1+o_i); latent=o_i*inv; correct=fma(o_i,s1,gg)*inv
// C has no backward deps -> ptxas pipelines it into B's stall slots.
// Outputs: direct strided STG.128 (R2 vs R3 showed staging is not needed).
// ---------------------------------------------------------------------------
__device__ __forceinline__ unsigned smem_u32(const void* p) {
    return (unsigned)__cvta_generic_to_shared(p);
}

__global__ __launch_bounds__(64) void bkt_kernel(
    const int* __restrict__ y, float* __restrict__ out)
{
    __shared__ __align__(16) int s_y[2][2][32][YP];

    const int warp = threadIdx.x >> 5;
    const int lane = threadIdx.x & 31;
    const int rowbase = (blockIdx.x * 2 + warp) * 32;
    const int row = rowbase + lane;

    const float A0 = g_A0[row];
    const float A1 = g_A1[row];
    const float Bc = g_B[row];
    const float s1 = g_s1[row];
    const float gg = g_gg[row];
    const float OMAX = (1.0f - EPSF) / EPSF;
    float o = g_o0[row];

    const int lr = lane >> 2;
    const int lc = (lane & 3) * 4;
    const int* yw = y + (size_t)rowbase * T_LEN;

#define LOAD_TILE(K, B) do {                                                  \
        _Pragma("unroll")                                                     \
        for (int i = 0; i < 4; ++i) {                                         \
            const int rr = 8 * i + lr;                                        \
            const int* src = yw + (size_t)rr * T_LEN + (K) * TILE + lc;       \
            unsigned dst = smem_u32(&s_y[warp][(B)][rr][lc]);                 \
            asm volatile("cp.async.cg.shared.global [%0], [%1], 16;"          \
                         :: "r"(dst), "l"(src));                              \
        }                                                                     \
        asm volatile("cp.async.commit_group;" ::: "memory");                  \
    } while (0)

    LOAD_TILE(0, 0);
    LOAD_TILE(1, 1);

    float* const outc = out + (size_t)row * T_LEN;
    float* const outl = out + (size_t)NUM_B * T_LEN + (size_t)row * T_LEN;

#pragma unroll 1
    for (int k = 0; k < NTILE; ++k) {
        const int b = k & 1;
        asm volatile("cp.async.wait_group 1;" ::: "memory");
        __syncwarp();

        // ---- Phase A: tile inputs -> A[16] (independent of chain) ----
        const int4 q0 = *reinterpret_cast<const int4*>(&s_y[warp][b][lane][0]);
        const int4 q1 = *reinterpret_cast<const int4*>(&s_y[warp][b][lane][4]);
        const int4 q2 = *reinterpret_cast<const int4*>(&s_y[warp][b][lane][8]);
        const int4 q3 = *reinterpret_cast<const int4*>(&s_y[warp][b][lane][12]);
        __syncwarp();   // lanes done with s_y[b]; safe to refill below

        float A[TILE];
        A[0]  = (q0.x > 0) ? A1 : A0;  A[1]  = (q0.y > 0) ? A1 : A0;
        A[2]  = (q0.z > 0) ? A1 : A0;  A[3]  = (q0.w > 0) ? A1 : A0;
        A[4]  = (q1.x > 0) ? A1 : A0;  A[5]  = (q1.y > 0) ? A1 : A0;
        A[6]  = (q1.z > 0) ? A1 : A0;  A[7]  = (q1.w > 0) ? A1 : A0;
        A[8]  = (q2.x > 0) ? A1 : A0;  A[9]  = (q2.y > 0) ? A1 : A0;
        A[10] = (q2.z > 0) ? A1 : A0;  A[11] = (q2.w > 0) ? A1 : A0;
        A[12] = (q3.x > 0) ? A1 : A0;  A[13] = (q3.y > 0) ? A1 : A0;
        A[14] = (q3.z > 0) ? A1 : A0;  A[15] = (q3.w > 0) ? A1 : A0;

        // refill early so LDGSTS issue overlaps the chain
        if (k < NTILE - 2) LOAD_TILE(k + 2, b);
        else asm volatile("cp.async.commit_group;" ::: "memory");

        // ---- Phase B: pure affine chain (FFMA + FMNMX per step) ----
        float oarr[TILE];
#pragma unroll
        for (int i = 0; i < TILE; ++i) {
            oarr[i] = o;
            o = fminf(fmaf(A[i], o, Bc), OMAX);
        }

        // ---- Phase C: per-step outputs (independent; fills B's stalls) ----
#pragma unroll
        for (int s = 0; s < 4; ++s) {
            float4 cv, lv;
            {   float ov = oarr[4*s+0], inv;
                asm("rcp.approx.ftz.f32 %0, %1;" : "=f"(inv) : "f"(1.0f + ov));
                lv.x = ov * inv;  cv.x = fmaf(ov, s1, gg) * inv; }
            {   float ov = oarr[4*s+1], inv;
                asm("rcp.approx.ftz.f32 %0, %1;" : "=f"(inv) : "f"(1.0f + ov));
                lv.y = ov * inv;  cv.y = fmaf(ov, s1, gg) * inv; }
            {   float ov = oarr[4*s+2], inv;
                asm("rcp.approx.ftz.f32 %0, %1;" : "=f"(inv) : "f"(1.0f + ov));
                lv.z = ov * inv;  cv.z = fmaf(ov, s1, gg) * inv; }
            {   float ov = oarr[4*s+3], inv;
                asm("rcp.approx.ftz.f32 %0, %1;" : "=f"(inv) : "f"(1.0f + ov));
                lv.w = ov * inv;  cv.w = fmaf(ov, s1, gg) * inv; }
            *reinterpret_cast<float4*>(outc + k * TILE + 4 * s) = cv;
            *reinterpret_cast<float4*>(outl + k * TILE + 4 * s) = lv;
        }
    }
#undef LOAD_TILE
}

// ---------------------------------------------------------------------------
extern "C" void kernel_launch(void* const* d_in, const int* in_sizes, int n_in,
                              void* d_out, int out_size)
{
    const int*   X     = (const int*)  d_in[0];
    const int*   y     = (const int*)  d_in[1];
    const float* embed = (const float*)d_in[2];
    const float* W0    = (const float*)d_in[3];
    const float* b0    = (const float*)d_in[4];
    const float* W1    = (const float*)d_in[5];
    const float* b1    = (const float*)d_in[6];
    const float* Wout  = (const float*)d_in[7];
    const float* bout  = (const float*)d_in[8];

    mlp_kernel<<<NUM_B / 8, 512>>>(X, embed, W0, b0, W1, b1, Wout, bout);
    bkt_kernel<<<NUM_B / 64, 64>>>(y, (float*)d_out);
}

// round 6
// speedup vs baseline: 1.5583x; 1.1082x over previous
#include <cuda_runtime.h>
#include <math.h>

#define NUM_B 8192
#define T_LEN 1024
#define HID   64
#define EPSF  1e-6f
#define SEGS  32              // one segment per lane
#define SLEN  (T_LEN / SEGS)  // 32 steps per segment
#define OPITCH 33             // smem pitch per lane-segment (conflict-free)

// Per-row scan constants (odds-space affine recurrence).
__device__ float g_A0[NUM_B], g_A1[NUM_B], g_B[NUM_B],
                 g_o0[NUM_B], g_s1[NUM_B], g_gg[NUM_B];

// ---------------------------------------------------------------------------
// Kernel 1: embed gather + MLP + sigmoid head + odds-space constants.
// ---------------------------------------------------------------------------
__global__ __launch_bounds__(512) void mlp_kernel(
    const int*   __restrict__ X,
    const float* __restrict__ embed,
    const float* __restrict__ W0, const float* __restrict__ b0,
    const float* __restrict__ W1, const float* __restrict__ b1,
    const float* __restrict__ Wout, const float* __restrict__ bout)
{
    __shared__ float sW0[HID * HID];
    __shared__ float sW1[HID * HID];
    __shared__ float sWo[HID * 4];
    __shared__ float sb0[HID], sb1[HID], sbo[4];
    __shared__ float sh[8][HID];
    __shared__ float sp[8][4];

    const int t = threadIdx.x;
    for (int i = t; i < HID * HID; i += 512) { sW0[i] = W0[i]; sW1[i] = W1[i]; }
    if (t < HID * 4) sWo[t] = Wout[t];
    if (t < HID)    { sb0[t] = b0[t]; sb1[t] = b1[t]; }
    if (t < 4)       sbo[t] = bout[t];

    const int j   = t & 63;
    const int r   = t >> 6;
    const int row = blockIdx.x * 8 + r;

    const int xi = X[row];
    sh[r][j] = embed[(size_t)xi * HID + j];
    __syncthreads();

    float acc = sb0[j];
#pragma unroll
    for (int i = 0; i < HID; i++) acc = fmaf(sh[r][i], sW0[i * HID + j], acc);
    acc = fmaxf(acc, 0.0f);
    __syncthreads();
    sh[r][j] = acc;
    __syncthreads();

    float acc1 = sb1[j];
#pragma unroll
    for (int i = 0; i < HID; i++) acc1 = fmaf(sh[r][i], sW1[i * HID + j], acc1);
    acc1 = fmaxf(acc1, 0.0f);
    __syncthreads();
    sh[r][j] = acc1;
    __syncthreads();

    if (j < 4) {
        float acc2 = sbo[j];
#pragma unroll
        for (int i = 0; i < HID; i++) acc2 = fmaf(sh[r][i], sWo[i * 4 + j], acc2);
        float pv = 1.0f / (1.0f + expf(-acc2));
        pv = fminf(fmaxf(pv, EPSF), 1.0f - EPSF);
        sp[r][j] = pv;
    }
    __syncthreads();

    if (j == 0) {
        const float l  = sp[r][0];
        const float gg = sp[r][1];
        const float s  = sp[r][2];
        const float pr = sp[r][3];
        const float il = 1.0f / (1.0f - l);
        g_A1[row] = (1.0f - s) / (gg * (1.0f - l));
        g_A0[row] = s / ((1.0f - gg) * (1.0f - l));
        g_B[row]  = l * il;
        g_o0[row] = pr / (1.0f - pr);
        g_s1[row] = 1.0f - s;
        g_gg[row] = gg;
    }
}

// ---------------------------------------------------------------------------
// Kernel 2: BKT scan, ONE WARP PER ROW via affine-with-cap map composition.
//   map f(o) = min(a*o + b, c);   f2∘f1 = (a2*a1, a2*b1+b2, min(a2*c1+b2, c2))
// Lane s owns steps [32s, 32s+32):
//   1) y -> per-lane bitmask via 32 coalesced LDG + ballot
//   2) compose segment map (3 FFMA chains + min)
//   3) Kogge-Stone inclusive warp scan of maps; o_start from lane-1
//   4) emit 32 steps (identical per-step math to prior passing kernel),
//      stage outputs in pitch-33 smem, drain coalesced.
// ---------------------------------------------------------------------------
__global__ __launch_bounds__(128) void bkt_kernel(
    const int* __restrict__ y, float* __restrict__ out)
{
    __shared__ float s_c[4][SEGS * OPITCH];   // 4224B per warp
    __shared__ float s_l[4][SEGS * OPITCH];

    const int w    = threadIdx.x >> 5;
    const int lane = threadIdx.x & 31;
    const int row  = blockIdx.x * 4 + w;

    const float A0 = g_A0[row];
    const float A1 = g_A1[row];
    const float Bc = g_B[row];
    const float s1 = g_s1[row];
    const float gg = g_gg[row];
    const float o0 = g_o0[row];
    const float OMAX = (1.0f - EPSF) / EPSF;

    // ---- 1) build per-lane y bitmask (coalesced loads + ballot) ----
    const int* yrow = y + (size_t)row * T_LEN;
    unsigned mask = 0;
#pragma unroll 8
    for (int c = 0; c < SEGS; ++c) {
        const int v = yrow[c * SLEN + lane];
        const unsigned m = __ballot_sync(0xffffffffu, v > 0);
        if (lane == c) mask = m;
    }

    // ---- 2) compose this lane's segment map ----
    float a = 1.0f, b = 0.0f, cc = OMAX;
#pragma unroll
    for (int j = 0; j < SLEN; ++j) {
        const float A = ((mask >> j) & 1u) ? A1 : A0;
        cc = fminf(fmaf(A, cc, Bc), OMAX);
        b  = fmaf(A, b, Bc);
        a  = A * a;
    }

    // ---- 3) inclusive Kogge-Stone scan over maps (cur ∘ prev) ----
#pragma unroll
    for (int d = 1; d < 32; d <<= 1) {
        const float ap = __shfl_up_sync(0xffffffffu, a,  d);
        const float bp = __shfl_up_sync(0xffffffffu, b,  d);
        const float cp = __shfl_up_sync(0xffffffffu, cc, d);
        if (lane >= d) {
            const float bn = fmaf(a, bp, b);
            const float cn = fminf(fmaf(a, cp, b), cc);
            a  = a * ap;
            b  = bn;
            cc = cn;
        }
    }
    const float ap = __shfl_up_sync(0xffffffffu, a,  1);
    const float bp = __shfl_up_sync(0xffffffffu, b,  1);
    const float cp = __shfl_up_sync(0xffffffffu, cc, 1);
    float o = (lane == 0) ? o0 : fminf(fmaf(ap, o0, bp), cp);  // fminf is NaN-safe

    // ---- 4) emit: 32 steps, outputs to conflict-free smem staging ----
    float* const sl = &s_l[w][lane * OPITCH];
    float* const sc = &s_c[w][lane * OPITCH];
#pragma unroll
    for (int j = 0; j < SLEN; ++j) {
        const float A = ((mask >> j) & 1u) ? A1 : A0;
        float inv;
        asm("rcp.approx.ftz.f32 %0, %1;" : "=f"(inv) : "f"(1.0f + o));
        sl[j] = o * inv;
        sc[j] = fmaf(o, s1, gg) * inv;
        o = fminf(fmaf(A, o, Bc), OMAX);
    }
    __syncwarp();

    // ---- drain coalesced: segment d's 32 values -> contiguous global ----
    float* const outc = out + (size_t)row * T_LEN;
    float* const outl = out + (size_t)NUM_B * T_LEN + (size_t)row * T_LEN;
#pragma unroll 8
    for (int d = 0; d < SEGS; ++d) {
        outc[d * SLEN + lane] = s_c[w][d * OPITCH + lane];
        outl[d * SLEN + lane] = s_l[w][d * OPITCH + lane];
    }
}

// ---------------------------------------------------------------------------
extern "C" void kernel_launch(void* const* d_in, const int* in_sizes, int n_in,
                              void* d_out, int out_size)
{
    const int*   X     = (const int*)  d_in[0];
    const int*   y     = (const int*)  d_in[1];
    const float* embed = (const float*)d_in[2];
    const float* W0    = (const float*)d_in[3];
    const float* b0    = (const float*)d_in[4];
    const float* W1    = (const float*)d_in[5];
    const float* b1    = (const float*)d_in[6];
    const float* Wout  = (const float*)d_in[7];
    const float* bout  = (const float*)d_in[8];

    mlp_kernel<<<NUM_B / 8, 512>>>(X, embed, W0, b0, W1, b1, Wout, bout);
    bkt_kernel<<<NUM_B / 4, 128>>>(y, (float*)d_out);
}

// round 7
// speedup vs baseline: 2.1492x; 1.3792x over previous
#include <cuda_runtime.h>
#include <math.h>

#define NUM_B 8192
#define T_LEN 1024
#define HID   64
#define EPSF  1e-6f
#define SEGS  32
#define SLEN  (T_LEN / SEGS)
#define OPITCH 33
#define HPITCH 68    // sh row pitch: 16B-aligned for c4 multiples of 4? (c4*4B mult of 16) yes

// Per-row scan constants (odds-space affine recurrence).
__device__ float g_A0[NUM_B], g_A1[NUM_B], g_B[NUM_B],
                 g_o0[NUM_B], g_s1[NUM_B], g_gg[NUM_B];

// ---------------------------------------------------------------------------
// Kernel 1: register-tiled MLP. 128 threads = 16 rows x 8 col-threads.
// Thread owns cols {c4..c4+3, c4+32..c4+35} (two conflict-free float4 loads).
// ---------------------------------------------------------------------------
__global__ __launch_bounds__(128) void mlp_kernel(
    const int*   __restrict__ X,
    const float* __restrict__ embed,
    const float* __restrict__ W0, const float* __restrict__ b0,
    const float* __restrict__ W1, const float* __restrict__ b1,
    const float* __restrict__ Wout, const float* __restrict__ bout)
{
    __shared__ float sW0[HID * HID];
    __shared__ float sW1[HID * HID];
    __shared__ float sWo[HID * 4];
    __shared__ float sb0[HID], sb1[HID], sbo[4];
    __shared__ float sh[16][HPITCH];
    __shared__ float sp[16][4];

    const int t = threadIdx.x;

    // stage weights (float4)
#pragma unroll
    for (int i = t; i < HID * HID / 4; i += 128) {
        reinterpret_cast<float4*>(sW0)[i] = reinterpret_cast<const float4*>(W0)[i];
        reinterpret_cast<float4*>(sW1)[i] = reinterpret_cast<const float4*>(W1)[i];
    }
    if (t < HID) { sb0[t] = b0[t]; sb1[t] = b1[t]; }
    if (t < HID) reinterpret_cast<float4*>(sWo)[t] = reinterpret_cast<const float4*>(Wout)[t];
    if (t < 4)   sbo[t] = bout[t];

    const int r   = t >> 3;          // 0..15
    const int c4  = (t & 7) * 4;     // 0,4,...,28
    const int row = blockIdx.x * 16 + r;

    // embed gather -> sh
    {
        const int xi = X[row];
        const float4 e0 = *reinterpret_cast<const float4*>(&embed[(size_t)xi * HID + c4]);
        const float4 e1 = *reinterpret_cast<const float4*>(&embed[(size_t)xi * HID + c4 + 32]);
        *reinterpret_cast<float4*>(&sh[r][c4])      = e0;
        *reinterpret_cast<float4*>(&sh[r][c4 + 32]) = e1;
    }
    __syncthreads();

    float acc[8];
#pragma unroll
    for (int k = 0; k < 4; ++k) { acc[k] = sb0[c4 + k]; acc[4 + k] = sb0[c4 + 32 + k]; }
#pragma unroll
    for (int i = 0; i < HID; ++i) {
        const float hb = sh[r][i];
        const float4 w0 = *reinterpret_cast<const float4*>(&sW0[i * HID + c4]);
        const float4 w1 = *reinterpret_cast<const float4*>(&sW0[i * HID + c4 + 32]);
        acc[0] = fmaf(hb, w0.x, acc[0]); acc[1] = fmaf(hb, w0.y, acc[1]);
        acc[2] = fmaf(hb, w0.z, acc[2]); acc[3] = fmaf(hb, w0.w, acc[3]);
        acc[4] = fmaf(hb, w1.x, acc[4]); acc[5] = fmaf(hb, w1.y, acc[5]);
        acc[6] = fmaf(hb, w1.z, acc[6]); acc[7] = fmaf(hb, w1.w, acc[7]);
    }
    __syncthreads();
    {
        float4 h0, h1;
        h0.x = fmaxf(acc[0], 0.0f); h0.y = fmaxf(acc[1], 0.0f);
        h0.z = fmaxf(acc[2], 0.0f); h0.w = fmaxf(acc[3], 0.0f);
        h1.x = fmaxf(acc[4], 0.0f); h1.y = fmaxf(acc[5], 0.0f);
        h1.z = fmaxf(acc[6], 0.0f); h1.w = fmaxf(acc[7], 0.0f);
        *reinterpret_cast<float4*>(&sh[r][c4])      = h0;
        *reinterpret_cast<float4*>(&sh[r][c4 + 32]) = h1;
    }
    __syncthreads();

#pragma unroll
    for (int k = 0; k < 4; ++k) { acc[k] = sb1[c4 + k]; acc[4 + k] = sb1[c4 + 32 + k]; }
#pragma unroll
    for (int i = 0; i < HID; ++i) {
        const float hb = sh[r][i];
        const float4 w0 = *reinterpret_cast<const float4*>(&sW1[i * HID + c4]);
        const float4 w1 = *reinterpret_cast<const float4*>(&sW1[i * HID + c4 + 32]);
        acc[0] = fmaf(hb, w0.x, acc[0]); acc[1] = fmaf(hb, w0.y, acc[1]);
        acc[2] = fmaf(hb, w0.z, acc[2]); acc[3] = fmaf(hb, w0.w, acc[3]);
        acc[4] = fmaf(hb, w1.x, acc[4]); acc[5] = fmaf(hb, w1.y, acc[5]);
        acc[6] = fmaf(hb, w1.z, acc[6]); acc[7] = fmaf(hb, w1.w, acc[7]);
    }
    __syncthreads();
    {
        float4 h0, h1;
        h0.x = fmaxf(acc[0], 0.0f); h0.y = fmaxf(acc[1], 0.0f);
        h0.z = fmaxf(acc[2], 0.0f); h0.w = fmaxf(acc[3], 0.0f);
        h1.x = fmaxf(acc[4], 0.0f); h1.y = fmaxf(acc[5], 0.0f);
        h1.z = fmaxf(acc[6], 0.0f); h1.w = fmaxf(acc[7], 0.0f);
        *reinterpret_cast<float4*>(&sh[r][c4])      = h0;
        *reinterpret_cast<float4*>(&sh[r][c4 + 32]) = h1;
    }
    __syncthreads();

    // head: 64 threads, (row, out-unit)
    if (t < 64) {
        const int r2 = t >> 2;
        const int jo = t & 3;
        float a2 = sbo[jo];
#pragma unroll
        for (int i = 0; i < HID; ++i) a2 = fmaf(sh[r2][i], sWo[i * 4 + jo], a2);
        float pv = 1.0f / (1.0f + expf(-a2));
        pv = fminf(fmaxf(pv, EPSF), 1.0f - EPSF);
        sp[r2][jo] = pv;
    }
    __syncthreads();

    if (t < 16) {
        const int rr  = blockIdx.x * 16 + t;
        const float l  = sp[t][0];
        const float gg = sp[t][1];
        const float s  = sp[t][2];
        const float pr = sp[t][3];
        const float il = 1.0f / (1.0f - l);
        g_A1[rr] = (1.0f - s) / (gg * (1.0f - l));
        g_A0[rr] = s / ((1.0f - gg) * (1.0f - l));
        g_B[rr]  = l * il;
        g_o0[rr] = pr / (1.0f - pr);
        g_s1[rr] = 1.0f - s;
        g_gg[rr] = gg;
    }
}

// ---------------------------------------------------------------------------
// Kernel 2: warp-per-row BKT scan (affine-with-cap map composition).
// Single staging plane (o only); latent/correct computed in the drain, where
// all constants are warp-uniform. Halved smem -> ~2x occupancy.
// ---------------------------------------------------------------------------
__global__ __launch_bounds__(128) void bkt_kernel(
    const int* __restrict__ y, float* __restrict__ out)
{
    __shared__ float s_o[4][SEGS * OPITCH];   // 16.9 KB

    const int w    = threadIdx.x >> 5;
    const int lane = threadIdx.x & 31;
    const int row  = blockIdx.x * 4 + w;

    const float A0 = g_A0[row];
    const float A1 = g_A1[row];
    const float Bc = g_B[row];
    const float s1 = g_s1[row];
    const float gg = g_gg[row];
    const float o0 = g_o0[row];
    const float OMAX = (1.0f - EPSF) / EPSF;

    // 1) per-lane y bitmask via coalesced loads + ballot
    const int* yrow = y + (size_t)row * T_LEN;
    unsigned mask = 0;
#pragma unroll 8
    for (int c = 0; c < SEGS; ++c) {
        const int v = yrow[c * SLEN + lane];
        const unsigned m = __ballot_sync(0xffffffffu, v > 0);
        if (lane == c) mask = m;
    }

    // 2) compose segment map f(o) = min(a*o + b, c)
    float a = 1.0f, b = 0.0f, cc = OMAX;
#pragma unroll
    for (int j = 0; j < SLEN; ++j) {
        const float A = ((mask >> j) & 1u) ? A1 : A0;
        cc = fminf(fmaf(A, cc, Bc), OMAX);
        b  = fmaf(A, b, Bc);
        a  = A * a;
    }

    // 3) inclusive Kogge-Stone scan over maps
#pragma unroll
    for (int d = 1; d < 32; d <<= 1) {
        const float ap = __shfl_up_sync(0xffffffffu, a,  d);
        const float bp = __shfl_up_sync(0xffffffffu, b,  d);
        const float cp = __shfl_up_sync(0xffffffffu, cc, d);
        if (lane >= d) {
            const float bn = fmaf(a, bp, b);
            const float cn = fminf(fmaf(a, cp, b), cc);
            a  = a * ap;
            b  = bn;
            cc = cn;
        }
    }
    const float ap = __shfl_up_sync(0xffffffffu, a,  1);
    const float bp = __shfl_up_sync(0xffffffffu, b,  1);
    const float cp = __shfl_up_sync(0xffffffffu, cc, 1);
    float o = (lane == 0) ? o0 : fminf(fmaf(ap, o0, bp), cp);

    // 4) emit: store pre-update o per step (single plane)
    float* const so = &s_o[w][lane * OPITCH];
#pragma unroll
    for (int j = 0; j < SLEN; ++j) {
        const float A = ((mask >> j) & 1u) ? A1 : A0;
        so[j] = o;
        o = fminf(fmaf(A, o, Bc), OMAX);
    }
    __syncwarp();

    // 5) drain: compute latent/correct from o (constants warp-uniform)
    float* const outc = out + (size_t)row * T_LEN;
    float* const outl = out + (size_t)NUM_B * T_LEN + (size_t)row * T_LEN;
#pragma unroll 8
    for (int d = 0; d < SEGS; ++d) {
        const float ov = s_o[w][d * OPITCH + lane];
        float inv;
        asm("rcp.approx.ftz.f32 %0, %1;" : "=f"(inv) : "f"(1.0f + ov));
        outl[d * SLEN + lane] = ov * inv;
        outc[d * SLEN + lane] = fmaf(ov, s1, gg) * inv;
    }
}

// ---------------------------------------------------------------------------
extern "C" void kernel_launch(void* const* d_in, const int* in_sizes, int n_in,
                              void* d_out, int out_size)
{
    const int*   X     = (const int*)  d_in[0];
    const int*   y     = (const int*)  d_in[1];
    const float* embed = (const float*)d_in[2];
    const float* W0    = (const float*)d_in[3];
    const float* b0    = (const float*)d_in[4];
    const float* W1    = (const float*)d_in[5];
    const float* b1    = (const float*)d_in[6];
    const float* Wout  = (const float*)d_in[7];
    const float* bout  = (const float*)d_in[8];

    mlp_kernel<<<NUM_B / 16, 128>>>(X, embed, W0, b0, W1, b1, Wout, bout);
    bkt_kernel<<<NUM_B / 4, 128>>>(y, (float*)d_out);
}

// round 8
// speedup vs baseline: 2.1659x; 1.0078x over previous
#include <cuda_runtime.h>
#include <math.h>

#define NUM_B 8192
#define T_LEN 1024
#define HID   64
#define EPSF  1e-6f
#define SEGS  32
#define SLEN  (T_LEN / SEGS)
#define OPITCH 36     // words; 16B-aligned rows, conflict-free STS.128/LDS.128 phases
#define HPITCH 68

// Per-row scan constants (odds-space affine recurrence).
__device__ float g_A0[NUM_B], g_A1[NUM_B], g_B[NUM_B],
                 g_o0[NUM_B], g_s1[NUM_B], g_gg[NUM_B];

// ---------------------------------------------------------------------------
// Kernel 1: register-tiled MLP. 256 blocks x 256 threads, 32 rows/block.
// W0/W1 staged sequentially through ONE 16KB smem buffer.
// Thread layout: r = t>>3 (row 0..31), c4 = (t&7)*4 (owns cols c4..+3, c4+32..+35).
// ---------------------------------------------------------------------------
__global__ __launch_bounds__(256) void mlp_kernel(
    const int*   __restrict__ X,
    const float* __restrict__ embed,
    const float* __restrict__ W0, const float* __restrict__ b0,
    const float* __restrict__ W1, const float* __restrict__ b1,
    const float* __restrict__ Wout, const float* __restrict__ bout)
{
    __shared__ float sW[HID * HID];          // 16 KB, reused for W0 then W1
    __shared__ float sWo[HID * 4];
    __shared__ float sb0[HID], sb1[HID], sbo[4];
    __shared__ float sh[32][HPITCH];
    __shared__ float sp[32][4];

    const int t = threadIdx.x;
    const int r   = t >> 3;          // 0..31
    const int c4  = (t & 7) * 4;     // 0..28
    const int row = blockIdx.x * 32 + r;

    // stage W0 (1024 float4, 4 per thread) + small tensors
#pragma unroll
    for (int i = t; i < HID * HID / 4; i += 256)
        reinterpret_cast<float4*>(sW)[i] = reinterpret_cast<const float4*>(W0)[i];
    if (t < HID) { sb0[t] = b0[t]; sb1[t] = b1[t]; }
    if (t < HID) reinterpret_cast<float4*>(sWo)[t] = reinterpret_cast<const float4*>(Wout)[t];
    if (t < 4)   sbo[t] = bout[t];

    // embed gather -> sh
    {
        const int xi = X[row];
        const float4 e0 = *reinterpret_cast<const float4*>(&embed[(size_t)xi * HID + c4]);
        const float4 e1 = *reinterpret_cast<const float4*>(&embed[(size_t)xi * HID + c4 + 32]);
        *reinterpret_cast<float4*>(&sh[r][c4])      = e0;
        *reinterpret_cast<float4*>(&sh[r][c4 + 32]) = e1;
    }
    __syncthreads();

    float acc[8];
#pragma unroll
    for (int k = 0; k < 4; ++k) { acc[k] = sb0[c4 + k]; acc[4 + k] = sb0[c4 + 32 + k]; }
#pragma unroll
    for (int i = 0; i < HID; ++i) {
        const float hb = sh[r][i];
        const float4 w0 = *reinterpret_cast<const float4*>(&sW[i * HID + c4]);
        const float4 w1 = *reinterpret_cast<const float4*>(&sW[i * HID + c4 + 32]);
        acc[0] = fmaf(hb, w0.x, acc[0]); acc[1] = fmaf(hb, w0.y, acc[1]);
        acc[2] = fmaf(hb, w0.z, acc[2]); acc[3] = fmaf(hb, w0.w, acc[3]);
        acc[4] = fmaf(hb, w1.x, acc[4]); acc[5] = fmaf(hb, w1.y, acc[5]);
        acc[6] = fmaf(hb, w1.z, acc[6]); acc[7] = fmaf(hb, w1.w, acc[7]);
    }
    __syncthreads();   // everyone done reading sW(W0) and sh

    // write relu(h1) and stage W1 (both complete before next sync)
    {
        float4 h0, h1;
        h0.x = fmaxf(acc[0], 0.0f); h0.y = fmaxf(acc[1], 0.0f);
        h0.z = fmaxf(acc[2], 0.0f); h0.w = fmaxf(acc[3], 0.0f);
        h1.x = fmaxf(acc[4], 0.0f); h1.y = fmaxf(acc[5], 0.0f);
        h1.z = fmaxf(acc[6], 0.0f); h1.w = fmaxf(acc[7], 0.0f);
        *reinterpret_cast<float4*>(&sh[r][c4])      = h0;
        *reinterpret_cast<float4*>(&sh[r][c4 + 32]) = h1;
    }
#pragma unroll
    for (int i = t; i < HID * HID / 4; i += 256)
        reinterpret_cast<float4*>(sW)[i] = reinterpret_cast<const float4*>(W1)[i];
    __syncthreads();

#pragma unroll
    for (int k = 0; k < 4; ++k) { acc[k] = sb1[c4 + k]; acc[4 + k] = sb1[c4 + 32 + k]; }
#pragma unroll
    for (int i = 0; i < HID; ++i) {
        const float hb = sh[r][i];
        const float4 w0 = *reinterpret_cast<const float4*>(&sW[i * HID + c4]);
        const float4 w1 = *reinterpret_cast<const float4*>(&sW[i * HID + c4 + 32]);
        acc[0] = fmaf(hb, w0.x, acc[0]); acc[1] = fmaf(hb, w0.y, acc[1]);
        acc[2] = fmaf(hb, w0.z, acc[2]); acc[3] = fmaf(hb, w0.w, acc[3]);
        acc[4] = fmaf(hb, w1.x, acc[4]); acc[5] = fmaf(hb, w1.y, acc[5]);
        acc[6] = fmaf(hb, w1.z, acc[6]); acc[7] = fmaf(hb, w1.w, acc[7]);
    }
    __syncthreads();
    {
        float4 h0, h1;
        h0.x = fmaxf(acc[0], 0.0f); h0.y = fmaxf(acc[1], 0.0f);
        h0.z = fmaxf(acc[2], 0.0f); h0.w = fmaxf(acc[3], 0.0f);
        h1.x = fmaxf(acc[4], 0.0f); h1.y = fmaxf(acc[5], 0.0f);
        h1.z = fmaxf(acc[6], 0.0f); h1.w = fmaxf(acc[7], 0.0f);
        *reinterpret_cast<float4*>(&sh[r][c4])      = h0;
        *reinterpret_cast<float4*>(&sh[r][c4 + 32]) = h1;
    }
    __syncthreads();

    // head: 128 threads cover 32 rows x 4 out-units
    if (t < 128) {
        const int r2 = t >> 2;
        const int jo = t & 3;
        float a2 = sbo[jo];
#pragma unroll
        for (int i = 0; i < HID; ++i) a2 = fmaf(sh[r2][i], sWo[i * 4 + jo], a2);
        float pv = 1.0f / (1.0f + expf(-a2));
        pv = fminf(fmaxf(pv, EPSF), 1.0f - EPSF);
        sp[r2][jo] = pv;
    }
    __syncthreads();

    if (t < 32) {
        const int rr  = blockIdx.x * 32 + t;
        const float l  = sp[t][0];
        const float gg = sp[t][1];
        const float s  = sp[t][2];
        const float pr = sp[t][3];
        const float il = 1.0f / (1.0f - l);
        g_A1[rr] = (1.0f - s) / (gg * (1.0f - l));
        g_A0[rr] = s / ((1.0f - gg) * (1.0f - l));
        g_B[rr]  = l * il;
        g_o0[rr] = pr / (1.0f - pr);
        g_s1[rr] = 1.0f - s;
        g_gg[rr] = gg;
    }
}

// ---------------------------------------------------------------------------
// Kernel 2: warp-per-row BKT scan (affine-with-cap map composition).
// Emit: float4-batched STS.128 (8 per lane). Drain: LDS.128 + 2x STG.128 per
// 4-output group. Pitch 36 keeps both phases conflict-free per 8-lane phase.
// ---------------------------------------------------------------------------
__global__ __launch_bounds__(128) void bkt_kernel(
    const int* __restrict__ y, float* __restrict__ out)
{
    __shared__ __align__(16) float s_o[4][SEGS * OPITCH];   // 18.4 KB

    const int w    = threadIdx.x >> 5;
    const int lane = threadIdx.x & 31;
    const int row  = blockIdx.x * 4 + w;

    const float A0 = g_A0[row];
    const float A1 = g_A1[row];
    const float Bc = g_B[row];
    const float s1 = g_s1[row];
    const float gg = g_gg[row];
    const float o0 = g_o0[row];
    const float OMAX = (1.0f - EPSF) / EPSF;

    // 1) per-lane y bitmask via coalesced loads + ballot
    const int* yrow = y + (size_t)row * T_LEN;
    unsigned mask = 0;
#pragma unroll 8
    for (int c = 0; c < SEGS; ++c) {
        const int v = yrow[c * SLEN + lane];
        const unsigned m = __ballot_sync(0xffffffffu, v > 0);
        if (lane == c) mask = m;
    }

    // 2) compose segment map f(o) = min(a*o + b, c)
    float a = 1.0f, b = 0.0f, cc = OMAX;
#pragma unroll
    for (int j = 0; j < SLEN; ++j) {
        const float A = ((mask >> j) & 1u) ? A1 : A0;
        cc = fminf(fmaf(A, cc, Bc), OMAX);
        b  = fmaf(A, b, Bc);
        a  = A * a;
    }

    // 3) inclusive Kogge-Stone scan over maps
#pragma unroll
    for (int d = 1; d < 32; d <<= 1) {
        const float ap = __shfl_up_sync(0xffffffffu, a,  d);
        const float bp = __shfl_up_sync(0xffffffffu, b,  d);
        const float cp = __shfl_up_sync(0xffffffffu, cc, d);
        if (lane >= d) {
            const float bn = fmaf(a, bp, b);
            const float cn = fminf(fmaf(a, cp, b), cc);
            a  = a * ap;
            b  = bn;
            cc = cn;
        }
    }
    const float ap = __shfl_up_sync(0xffffffffu, a,  1);
    const float bp = __shfl_up_sync(0xffffffffu, b,  1);
    const float cp = __shfl_up_sync(0xffffffffu, cc, 1);
    float o = (lane == 0) ? o0 : fminf(fmaf(ap, o0, bp), cp);

    // 4) emit: batch 4 steps into float4, STS.128 (conflict-free phases)
    float* const so = &s_o[w][lane * OPITCH];
#pragma unroll
    for (int j4 = 0; j4 < SLEN / 4; ++j4) {
        float4 ov;
        {   const float A = ((mask >> (4*j4+0)) & 1u) ? A1 : A0;
            ov.x = o;  o = fminf(fmaf(A, o, Bc), OMAX); }
        {   const float A = ((mask >> (4*j4+1)) & 1u) ? A1 : A0;
            ov.y = o;  o = fminf(fmaf(A, o, Bc), OMAX); }
        {   const float A = ((mask >> (4*j4+2)) & 1u) ? A1 : A0;
            ov.z = o;  o = fminf(fmaf(A, o, Bc), OMAX); }
        {   const float A = ((mask >> (4*j4+3)) & 1u) ? A1 : A0;
            ov.w = o;  o = fminf(fmaf(A, o, Bc), OMAX); }
        *reinterpret_cast<float4*>(so + 4 * j4) = ov;
    }
    __syncwarp();

    // 5) drain: lane -> (segment sg, 4 cols k4); LDS.128 + 2x STG.128
    float* const outc = out + (size_t)row * T_LEN;
    float* const outl = out + (size_t)NUM_B * T_LEN + (size_t)row * T_LEN;
    const int sgl = lane >> 3;          // 0..3 segment sub-index
    const int k4  = (lane & 7) * 4;     // 0..28
#pragma unroll
    for (int dd = 0; dd < 8; ++dd) {
        const int seg = dd * 4 + sgl;
        const float4 ov = *reinterpret_cast<const float4*>(&s_o[w][seg * OPITCH + k4]);
        float4 lv, cv;
        float inv;
        asm("rcp.approx.ftz.f32 %0, %1;" : "=f"(inv) : "f"(1.0f + ov.x));
        lv.x = ov.x * inv;  cv.x = fmaf(ov.x, s1, gg) * inv;
        asm("rcp.approx.ftz.f32 %0, %1;" : "=f"(inv) : "f"(1.0f + ov.y));
        lv.y = ov.y * inv;  cv.y = fmaf(ov.y, s1, gg) * inv;
        asm("rcp.approx.ftz.f32 %0, %1;" : "=f"(inv) : "f"(1.0f + ov.z));
        lv.z = ov.z * inv;  cv.z = fmaf(ov.z, s1, gg) * inv;
        asm("rcp.approx.ftz.f32 %0, %1;" : "=f"(inv) : "f"(1.0f + ov.w));
        lv.w = ov.w * inv;  cv.w = fmaf(ov.w, s1, gg) * inv;
        *reinterpret_cast<float4*>(outc + seg * SLEN + k4) = cv;
        *reinterpret_cast<float4*>(outl + seg * SLEN + k4) = lv;
    }
}

// ---------------------------------------------------------------------------
extern "C" void kernel_launch(void* const* d_in, const int* in_sizes, int n_in,
                              void* d_out, int out_size)
{
    const int*   X     = (const int*)  d_in[0];
    const int*   y     = (const int*)  d_in[1];
    const float* embed = (const float*)d_in[2];
    const float* W0    = (const float*)d_in[3];
    const float* b0    = (const float*)d_in[4];
    const float* W1    = (const float*)d_in[5];
    const float* b1    = (const float*)d_in[6];
    const float* Wout  = (const float*)d_in[7];
    const float* bout  = (const float*)d_in[8];

    mlp_kernel<<<NUM_B / 32, 256>>>(X, embed, W0, b0, W1, b1, Wout, bout);
    bkt_kernel<<<NUM_B / 4, 128>>>(y, (float*)d_out);
}

// round 9
// speedup vs baseline: 2.2903x; 1.0574x over previous
#include <cuda_runtime.h>
#include <math.h>

#define NUM_B 8192
#define T_LEN 1024
#define HID   64
#define EPSF  1e-6f
#define SEGS  32
#define SLEN  (T_LEN / SEGS)
#define OPITCH 36
#define HPITCH 68
#define MROWS 64          // rows per MLP block

// Per-row scan constants (odds-space affine recurrence).
__device__ float g_A0[NUM_B], g_A1[NUM_B], g_B[NUM_B],
                 g_o0[NUM_B], g_s1[NUM_B], g_gg[NUM_B];

// ---------------------------------------------------------------------------
// Kernel 1: MLP, 4 rows/thread. 128 blocks x 128 threads, 64 rows/block.
// Thread (rg = t>>3, c4 = (t&7)*4) owns rows rg*4..+3, cols {c4..+3, c4+32..+35}.
// Each weight LDS.128 feeds 16 FFMA (4 rows) -> crossbar traffic /4 vs R8.
// ---------------------------------------------------------------------------
__global__ __launch_bounds__(128) void mlp_kernel(
    const int*   __restrict__ X,
    const float* __restrict__ embed,
    const float* __restrict__ W0, const float* __restrict__ b0,
    const float* __restrict__ W1, const float* __restrict__ b1,
    const float* __restrict__ Wout, const float* __restrict__ bout)
{
    __shared__ float sW[HID * HID];       // 16 KB, W0 then W1
    __shared__ float sWo[HID * 4];
    __shared__ float sb0[HID], sb1[HID], sbo[4];
    __shared__ float sh[MROWS][HPITCH];   // 17.4 KB
    __shared__ float sp[MROWS][4];

    const int t = threadIdx.x;

    // stage W0 + small tensors
#pragma unroll
    for (int i = t; i < HID * HID / 4; i += 128)
        reinterpret_cast<float4*>(sW)[i] = reinterpret_cast<const float4*>(W0)[i];
    if (t < HID) { sb0[t] = b0[t]; sb1[t] = b1[t]; }
    if (t < HID) reinterpret_cast<float4*>(sWo)[t] = reinterpret_cast<const float4*>(Wout)[t];
    if (t < 4)   sbo[t] = bout[t];

    const int c4    = (t & 7) * 4;
    const int rbase = (t >> 3) * 4;                 // 0,4,...,60
    const int growbase = blockIdx.x * MROWS;

    // embed gather: 4 rows x 2 float4 per thread
#pragma unroll
    for (int rr = 0; rr < 4; ++rr) {
        const int xi = X[growbase + rbase + rr];
        const float4 e0 = *reinterpret_cast<const float4*>(&embed[(size_t)xi * HID + c4]);
        const float4 e1 = *reinterpret_cast<const float4*>(&embed[(size_t)xi * HID + c4 + 32]);
        *reinterpret_cast<float4*>(&sh[rbase + rr][c4])      = e0;
        *reinterpret_cast<float4*>(&sh[rbase + rr][c4 + 32]) = e1;
    }
    __syncthreads();

    float acc[32];   // [row 0..3][col 0..7]

    // ---------------- layer 0 ----------------
#pragma unroll
    for (int rr = 0; rr < 4; ++rr)
#pragma unroll
        for (int k = 0; k < 4; ++k) {
            acc[rr * 8 + k]     = sb0[c4 + k];
            acc[rr * 8 + 4 + k] = sb0[c4 + 32 + k];
        }
#pragma unroll
    for (int i = 0; i < HID; ++i) {
        const float4 w0 = *reinterpret_cast<const float4*>(&sW[i * HID + c4]);
        const float4 w1 = *reinterpret_cast<const float4*>(&sW[i * HID + c4 + 32]);
#pragma unroll
        for (int rr = 0; rr < 4; ++rr) {
            const float hb = sh[rbase + rr][i];
            acc[rr*8+0] = fmaf(hb, w0.x, acc[rr*8+0]);
            acc[rr*8+1] = fmaf(hb, w0.y, acc[rr*8+1]);
            acc[rr*8+2] = fmaf(hb, w0.z, acc[rr*8+2]);
            acc[rr*8+3] = fmaf(hb, w0.w, acc[rr*8+3]);
            acc[rr*8+4] = fmaf(hb, w1.x, acc[rr*8+4]);
            acc[rr*8+5] = fmaf(hb, w1.y, acc[rr*8+5]);
            acc[rr*8+6] = fmaf(hb, w1.z, acc[rr*8+6]);
            acc[rr*8+7] = fmaf(hb, w1.w, acc[rr*8+7]);
        }
    }
    __syncthreads();   // done reading sW(W0) and sh

    // write relu(h1); stage W1
#pragma unroll
    for (int rr = 0; rr < 4; ++rr) {
        float4 h0, h1;
        h0.x = fmaxf(acc[rr*8+0], 0.0f); h0.y = fmaxf(acc[rr*8+1], 0.0f);
        h0.z = fmaxf(acc[rr*8+2], 0.0f); h0.w = fmaxf(acc[rr*8+3], 0.0f);
        h1.x = fmaxf(acc[rr*8+4], 0.0f); h1.y = fmaxf(acc[rr*8+5], 0.0f);
        h1.z = fmaxf(acc[rr*8+6], 0.0f); h1.w = fmaxf(acc[rr*8+7], 0.0f);
        *reinterpret_cast<float4*>(&sh[rbase + rr][c4])      = h0;
        *reinterpret_cast<float4*>(&sh[rbase + rr][c4 + 32]) = h1;
    }
#pragma unroll
    for (int i = t; i < HID * HID / 4; i += 128)
        reinterpret_cast<float4*>(sW)[i] = reinterpret_cast<const float4*>(W1)[i];
    __syncthreads();

    // ---------------- layer 1 ----------------
#pragma unroll
    for (int rr = 0; rr < 4; ++rr)
#pragma unroll
        for (int k = 0; k < 4; ++k) {
            acc[rr * 8 + k]     = sb1[c4 + k];
            acc[rr * 8 + 4 + k] = sb1[c4 + 32 + k];
        }
#pragma unroll
    for (int i = 0; i < HID; ++i) {
        const float4 w0 = *reinterpret_cast<const float4*>(&sW[i * HID + c4]);
        const float4 w1 = *reinterpret_cast<const float4*>(&sW[i * HID + c4 + 32]);
#pragma unroll
        for (int rr = 0; rr < 4; ++rr) {
            const float hb = sh[rbase + rr][i];
            acc[rr*8+0] = fmaf(hb, w0.x, acc[rr*8+0]);
            acc[rr*8+1] = fmaf(hb, w0.y, acc[rr*8+1]);
            acc[rr*8+2] = fmaf(hb, w0.z, acc[rr*8+2]);
            acc[rr*8+3] = fmaf(hb, w0.w, acc[rr*8+3]);
            acc[rr*8+4] = fmaf(hb, w1.x, acc[rr*8+4]);
            acc[rr*8+5] = fmaf(hb, w1.y, acc[rr*8+5]);
            acc[rr*8+6] = fmaf(hb, w1.z, acc[rr*8+6]);
            acc[rr*8+7] = fmaf(hb, w1.w, acc[rr*8+7]);
        }
    }
    __syncthreads();
#pragma unroll
    for (int rr = 0; rr < 4; ++rr) {
        float4 h0, h1;
        h0.x = fmaxf(acc[rr*8+0], 0.0f); h0.y = fmaxf(acc[rr*8+1], 0.0f);
        h0.z = fmaxf(acc[rr*8+2], 0.0f); h0.w = fmaxf(acc[rr*8+3], 0.0f);
        h1.x = fmaxf(acc[rr*8+4], 0.0f); h1.y = fmaxf(acc[rr*8+5], 0.0f);
        h1.z = fmaxf(acc[rr*8+6], 0.0f); h1.w = fmaxf(acc[rr*8+7], 0.0f);
        *reinterpret_cast<float4*>(&sh[rbase + rr][c4])      = h0;
        *reinterpret_cast<float4*>(&sh[rbase + rr][c4 + 32]) = h1;
    }
    __syncthreads();

    // head: thread -> row t>>1, units (t&1)*2, (t&1)*2+1
    {
        const int hr  = t >> 1;
        const int jo  = (t & 1) * 2;
        float a0 = sbo[jo], a1 = sbo[jo + 1];
#pragma unroll
        for (int i = 0; i < HID; ++i) {
            const float hb = sh[hr][i];
            a0 = fmaf(hb, sWo[i * 4 + jo],     a0);
            a1 = fmaf(hb, sWo[i * 4 + jo + 1], a1);
        }
        float p0 = 1.0f / (1.0f + expf(-a0));
        float p1 = 1.0f / (1.0f + expf(-a1));
        sp[hr][jo]     = fminf(fmaxf(p0, EPSF), 1.0f - EPSF);
        sp[hr][jo + 1] = fminf(fmaxf(p1, EPSF), 1.0f - EPSF);
    }
    __syncthreads();

    if (t < MROWS) {
        const int rr   = growbase + t;
        const float l  = sp[t][0];
        const float gg = sp[t][1];
        const float s  = sp[t][2];
        const float pr = sp[t][3];
        const float il = 1.0f / (1.0f - l);
        g_A1[rr] = (1.0f - s) / (gg * (1.0f - l));
        g_A0[rr] = s / ((1.0f - gg) * (1.0f - l));
        g_B[rr]  = l * il;
        g_o0[rr] = pr / (1.0f - pr);
        g_s1[rr] = 1.0f - s;
        g_gg[rr] = gg;
    }
}

// ---------------------------------------------------------------------------
// Kernel 2: warp-per-row BKT scan (identical to R8 passing version).
// ---------------------------------------------------------------------------
__global__ __launch_bounds__(128) void bkt_kernel(
    const int* __restrict__ y, float* __restrict__ out)
{
    __shared__ __align__(16) float s_o[4][SEGS * OPITCH];

    const int w    = threadIdx.x >> 5;
    const int lane = threadIdx.x & 31;
    const int row  = blockIdx.x * 4 + w;

    const float A0 = g_A0[row];
    const float A1 = g_A1[row];
    const float Bc = g_B[row];
    const float s1 = g_s1[row];
    const float gg = g_gg[row];
    const float o0 = g_o0[row];
    const float OMAX = (1.0f - EPSF) / EPSF;

    const int* yrow = y + (size_t)row * T_LEN;
    unsigned mask = 0;
#pragma unroll 8
    for (int c = 0; c < SEGS; ++c) {
        const int v = yrow[c * SLEN + lane];
        const unsigned m = __ballot_sync(0xffffffffu, v > 0);
        if (lane == c) mask = m;
    }

    float a = 1.0f, b = 0.0f, cc = OMAX;
#pragma unroll
    for (int j = 0; j < SLEN; ++j) {
        const float A = ((mask >> j) & 1u) ? A1 : A0;
        cc = fminf(fmaf(A, cc, Bc), OMAX);
        b  = fmaf(A, b, Bc);
        a  = A * a;
    }

#pragma unroll
    for (int d = 1; d < 32; d <<= 1) {
        const float ap = __shfl_up_sync(0xffffffffu, a,  d);
        const float bp = __shfl_up_sync(0xffffffffu, b,  d);
        const float cp = __shfl_up_sync(0xffffffffu, cc, d);
        if (lane >= d) {
            const float bn = fmaf(a, bp, b);
            const float cn = fminf(fmaf(a, cp, b), cc);
            a  = a * ap;
            b  = bn;
            cc = cn;
        }
    }
    const float ap = __shfl_up_sync(0xffffffffu, a,  1);
    const float bp = __shfl_up_sync(0xffffffffu, b,  1);
    const float cp = __shfl_up_sync(0xffffffffu, cc, 1);
    float o = (lane == 0) ? o0 : fminf(fmaf(ap, o0, bp), cp);

    float* const so = &s_o[w][lane * OPITCH];
#pragma unroll
    for (int j4 = 0; j4 < SLEN / 4; ++j4) {
        float4 ov;
        {   const float A = ((mask >> (4*j4+0)) & 1u) ? A1 : A0;
            ov.x = o;  o = fminf(fmaf(A, o, Bc), OMAX); }
        {   const float A = ((mask >> (4*j4+1)) & 1u) ? A1 : A0;
            ov.y = o;  o = fminf(fmaf(A, o, Bc), OMAX); }
        {   const float A = ((mask >> (4*j4+2)) & 1u) ? A1 : A0;
            ov.z = o;  o = fminf(fmaf(A, o, Bc), OMAX); }
        {   const float A = ((mask >> (4*j4+3)) & 1u) ? A1 : A0;
            ov.w = o;  o = fminf(fmaf(A, o, Bc), OMAX); }
        *reinterpret_cast<float4*>(so + 4 * j4) = ov;
    }
    __syncwarp();

    float* const outc = out + (size_t)row * T_LEN;
    float* const outl = out + (size_t)NUM_B * T_LEN + (size_t)row * T_LEN;
    const int sgl = lane >> 3;
    const int k4  = (lane & 7) * 4;
#pragma unroll
    for (int dd = 0; dd < 8; ++dd) {
        const int seg = dd * 4 + sgl;
        const float4 ov = *reinterpret_cast<const float4*>(&s_o[w][seg * OPITCH + k4]);
        float4 lv, cv;
        float inv;
        asm("rcp.approx.ftz.f32 %0, %1;" : "=f"(inv) : "f"(1.0f + ov.x));
        lv.x = ov.x * inv;  cv.x = fmaf(ov.x, s1, gg) * inv;
        asm("rcp.approx.ftz.f32 %0, %1;" : "=f"(inv) : "f"(1.0f + ov.y));
        lv.y = ov.y * inv;  cv.y = fmaf(ov.y, s1, gg) * inv;
        asm("rcp.approx.ftz.f32 %0, %1;" : "=f"(inv) : "f"(1.0f + ov.z));
        lv.z = ov.z * inv;  cv.z = fmaf(ov.z, s1, gg) * inv;
        asm("rcp.approx.ftz.f32 %0, %1;" : "=f"(inv) : "f"(1.0f + ov.w));
        lv.w = ov.w * inv;  cv.w = fmaf(ov.w, s1, gg) * inv;
        *reinterpret_cast<float4*>(outc + seg * SLEN + k4) = cv;
        *reinterpret_cast<float4*>(outl + seg * SLEN + k4) = lv;
    }
}

// ---------------------------------------------------------------------------
extern "C" void kernel_launch(void* const* d_in, const int* in_sizes, int n_in,
                              void* d_out, int out_size)
{
    const int*   X     = (const int*)  d_in[0];
    const int*   y     = (const int*)  d_in[1];
    const float* embed = (const float*)d_in[2];
    const float* W0    = (const float*)d_in[3];
    const float* b0    = (const float*)d_in[4];
    const float* W1    = (const float*)d_in[5];
    const float* b1    = (const float*)d_in[6];
    const float* Wout  = (const float*)d_in[7];
    const float* bout  = (const float*)d_in[8];

    mlp_kernel<<<NUM_B / MROWS, 128>>>(X, embed, W0, b0, W1, b1, Wout, bout);
    bkt_kernel<<<NUM_B / 4, 128>>>(y, (float*)d_out);
}

// round 10
// speedup vs baseline: 2.6333x; 1.1498x over previous
#include <cuda_runtime.h>
#include <math.h>

#define NUM_B 8192
#define T_LEN 1024
#define HID   64
#define EPSF  1e-6f
#define SEGS  32
#define SLEN  (T_LEN / SEGS)
#define OPITCH 36
#define HPITCH 68
#define MROWS 64
#define BWARPS 8          // bkt warps per block

// Per-row scan constants (odds-space affine recurrence).
__device__ float g_A0[NUM_B], g_A1[NUM_B], g_B[NUM_B],
                 g_o0[NUM_B], g_s1[NUM_B], g_gg[NUM_B];

// ---------------------------------------------------------------------------
// Kernel 1: MLP. 128 blocks x 256 threads (2 warps/SMSP), 64 rows/block,
// 2 rows/thread. Thread (rp = (t>>3)*2, c4 = (t&7)*4) owns rows rp..rp+1,
// cols {c4..+3, c4+32..+35}.
// ---------------------------------------------------------------------------
__global__ __launch_bounds__(256) void mlp_kernel(
    const int*   __restrict__ X,
    const float* __restrict__ embed,
    const float* __restrict__ W0, const float* __restrict__ b0,
    const float* __restrict__ W1, const float* __restrict__ b1,
    const float* __restrict__ Wout, const float* __restrict__ bout)
{
    __shared__ float sW[HID * HID];       // 16 KB, W0 then W1
    __shared__ float sWo[HID * 4];
    __shared__ float sb0[HID], sb1[HID], sbo[4];
    __shared__ float sh[MROWS][HPITCH];
    __shared__ float sp[MROWS][4];

    const int t = threadIdx.x;

#pragma unroll
    for (int i = t; i < HID * HID / 4; i += 256)
        reinterpret_cast<float4*>(sW)[i] = reinterpret_cast<const float4*>(W0)[i];
    if (t < HID) { sb0[t] = b0[t]; sb1[t] = b1[t]; }
    if (t < HID) reinterpret_cast<float4*>(sWo)[t] = reinterpret_cast<const float4*>(Wout)[t];
    if (t < 4)   sbo[t] = bout[t];

    const int c4 = (t & 7) * 4;
    const int rp = (t >> 3) * 2;               // 0,2,...,62
    const int growbase = blockIdx.x * MROWS;

    // embed gather: 2 rows x 2 float4 per thread
#pragma unroll
    for (int rr = 0; rr < 2; ++rr) {
        const int xi = X[growbase + rp + rr];
        const float4 e0 = *reinterpret_cast<const float4*>(&embed[(size_t)xi * HID + c4]);
        const float4 e1 = *reinterpret_cast<const float4*>(&embed[(size_t)xi * HID + c4 + 32]);
        *reinterpret_cast<float4*>(&sh[rp + rr][c4])      = e0;
        *reinterpret_cast<float4*>(&sh[rp + rr][c4 + 32]) = e1;
    }
    __syncthreads();

    float acc[16];   // [row 0..1][col 0..7]

    // ---------------- layer 0 ----------------
#pragma unroll
    for (int rr = 0; rr < 2; ++rr)
#pragma unroll
        for (int k = 0; k < 4; ++k) {
            acc[rr * 8 + k]     = sb0[c4 + k];
            acc[rr * 8 + 4 + k] = sb0[c4 + 32 + k];
        }
#pragma unroll
    for (int i = 0; i < HID; ++i) {
        const float4 w0 = *reinterpret_cast<const float4*>(&sW[i * HID + c4]);
        const float4 w1 = *reinterpret_cast<const float4*>(&sW[i * HID + c4 + 32]);
#pragma unroll
        for (int rr = 0; rr < 2; ++rr) {
            const float hb = sh[rp + rr][i];
            acc[rr*8+0] = fmaf(hb, w0.x, acc[rr*8+0]);
            acc[rr*8+1] = fmaf(hb, w0.y, acc[rr*8+1]);
            acc[rr*8+2] = fmaf(hb, w0.z, acc[rr*8+2]);
            acc[rr*8+3] = fmaf(hb, w0.w, acc[rr*8+3]);
            acc[rr*8+4] = fmaf(hb, w1.x, acc[rr*8+4]);
            acc[rr*8+5] = fmaf(hb, w1.y, acc[rr*8+5]);
            acc[rr*8+6] = fmaf(hb, w1.z, acc[rr*8+6]);
            acc[rr*8+7] = fmaf(hb, w1.w, acc[rr*8+7]);
        }
    }
    __syncthreads();

#pragma unroll
    for (int rr = 0; rr < 2; ++rr) {
        float4 h0, h1;
        h0.x = fmaxf(acc[rr*8+0], 0.0f); h0.y = fmaxf(acc[rr*8+1], 0.0f);
        h0.z = fmaxf(acc[rr*8+2], 0.0f); h0.w = fmaxf(acc[rr*8+3], 0.0f);
        h1.x = fmaxf(acc[rr*8+4], 0.0f); h1.y = fmaxf(acc[rr*8+5], 0.0f);
        h1.z = fmaxf(acc[rr*8+6], 0.0f); h1.w = fmaxf(acc[rr*8+7], 0.0f);
        *reinterpret_cast<float4*>(&sh[rp + rr][c4])      = h0;
        *reinterpret_cast<float4*>(&sh[rp + rr][c4 + 32]) = h1;
    }
#pragma unroll
    for (int i = t; i < HID * HID / 4; i += 256)
        reinterpret_cast<float4*>(sW)[i] = reinterpret_cast<const float4*>(W1)[i];
    __syncthreads();

    // ---------------- layer 1 ----------------
#pragma unroll
    for (int rr = 0; rr < 2; ++rr)
#pragma unroll
        for (int k = 0; k < 4; ++k) {
            acc[rr * 8 + k]     = sb1[c4 + k];
            acc[rr * 8 + 4 + k] = sb1[c4 + 32 + k];
        }
#pragma unroll
    for (int i = 0; i < HID; ++i) {
        const float4 w0 = *reinterpret_cast<const float4*>(&sW[i * HID + c4]);
        const float4 w1 = *reinterpret_cast<const float4*>(&sW[i * HID + c4 + 32]);
#pragma unroll
        for (int rr = 0; rr < 2; ++rr) {
            const float hb = sh[rp + rr][i];
            acc[rr*8+0] = fmaf(hb, w0.x, acc[rr*8+0]);
            acc[rr*8+1] = fmaf(hb, w0.y, acc[rr*8+1]);
            acc[rr*8+2] = fmaf(hb, w0.z, acc[rr*8+2]);
            acc[rr*8+3] = fmaf(hb, w0.w, acc[rr*8+3]);
            acc[rr*8+4] = fmaf(hb, w1.x, acc[rr*8+4]);
            acc[rr*8+5] = fmaf(hb, w1.y, acc[rr*8+5]);
            acc[rr*8+6] = fmaf(hb, w1.z, acc[rr*8+6]);
            acc[rr*8+7] = fmaf(hb, w1.w, acc[rr*8+7]);
        }
    }
    __syncthreads();
#pragma unroll
    for (int rr = 0; rr < 2; ++rr) {
        float4 h0, h1;
        h0.x = fmaxf(acc[rr*8+0], 0.0f); h0.y = fmaxf(acc[rr*8+1], 0.0f);
        h0.z = fmaxf(acc[rr*8+2], 0.0f); h0.w = fmaxf(acc[rr*8+3], 0.0f);
        h1.x = fmaxf(acc[rr*8+4], 0.0f); h1.y = fmaxf(acc[rr*8+5], 0.0f);
        h1.z = fmaxf(acc[rr*8+6], 0.0f); h1.w = fmaxf(acc[rr*8+7], 0.0f);
        *reinterpret_cast<float4*>(&sh[rp + rr][c4])      = h0;
        *reinterpret_cast<float4*>(&sh[rp + rr][c4 + 32]) = h1;
    }
    __syncthreads();

    // head: 256 threads = 64 rows x 4 units
    {
        const int hr = t >> 2;
        const int jo = t & 3;
        float a2 = sbo[jo];
#pragma unroll
        for (int i = 0; i < HID; ++i) a2 = fmaf(sh[hr][i], sWo[i * 4 + jo], a2);
        float pv = 1.0f / (1.0f + expf(-a2));
        sp[hr][jo] = fminf(fmaxf(pv, EPSF), 1.0f - EPSF);
    }
    __syncthreads();

    if (t < MROWS) {
        const int rr   = growbase + t;
        const float l  = sp[t][0];
        const float gg = sp[t][1];
        const float s  = sp[t][2];
        const float pr = sp[t][3];
        const float il = 1.0f / (1.0f - l);
        g_A1[rr] = (1.0f - s) / (gg * (1.0f - l));
        g_A0[rr] = s / ((1.0f - gg) * (1.0f - l));
        g_B[rr]  = l * il;
        g_o0[rr] = pr / (1.0f - pr);
        g_s1[rr] = 1.0f - s;
        g_gg[rr] = gg;
    }
}

// ---------------------------------------------------------------------------
// Kernel 2: warp-per-row BKT scan. 256 threads (8 warps), grid 1024.
// Mask build: preload 16 y values into regs (one latency exposure), then
// 16 ballots; twice. Rest identical to the R8/R9 passing structure.
// ---------------------------------------------------------------------------
__global__ __launch_bounds__(256) void bkt_kernel(
    const int* __restrict__ y, float* __restrict__ out)
{
    __shared__ __align__(16) float s_o[BWARPS][SEGS * OPITCH];   // 36.9 KB

    const int w    = threadIdx.x >> 5;
    const int lane = threadIdx.x & 31;
    const int row  = blockIdx.x * BWARPS + w;

    const float A0 = g_A0[row];
    const float A1 = g_A1[row];
    const float Bc = g_B[row];
    const float s1 = g_s1[row];
    const float gg = g_gg[row];
    const float o0 = g_o0[row];
    const float OMAX = (1.0f - EPSF) / EPSF;

    // 1) mask build: preload-then-ballot in two halves of 16
    const int* yrow = y + (size_t)row * T_LEN;
    unsigned mask = 0;
    {
        int v[16];
#pragma unroll
        for (int c = 0; c < 16; ++c) v[c] = yrow[c * SLEN + lane];
#pragma unroll
        for (int c = 0; c < 16; ++c) {
            const unsigned m = __ballot_sync(0xffffffffu, v[c] > 0);
            if (lane == c) mask = m;
        }
#pragma unroll
        for (int c = 0; c < 16; ++c) v[c] = yrow[(16 + c) * SLEN + lane];
#pragma unroll
        for (int c = 0; c < 16; ++c) {
            const unsigned m = __ballot_sync(0xffffffffu, v[c] > 0);
            if (lane == 16 + c) mask = m;
        }
    }

    // 2) compose segment map f(o) = min(a*o + b, c)
    float a = 1.0f, b = 0.0f, cc = OMAX;
#pragma unroll
    for (int j = 0; j < SLEN; ++j) {
        const float A = ((mask >> j) & 1u) ? A1 : A0;
        cc = fminf(fmaf(A, cc, Bc), OMAX);
        b  = fmaf(A, b, Bc);
        a  = A * a;
    }

    // 3) inclusive Kogge-Stone scan over maps
#pragma unroll
    for (int d = 1; d < 32; d <<= 1) {
        const float ap = __shfl_up_sync(0xffffffffu, a,  d);
        const float bp = __shfl_up_sync(0xffffffffu, b,  d);
        const float cp = __shfl_up_sync(0xffffffffu, cc, d);
        if (lane >= d) {
            const float bn = fmaf(a, bp, b);
            const float cn = fminf(fmaf(a, cp, b), cc);
            a  = a * ap;
            b  = bn;
            cc = cn;
        }
    }
    const float ap = __shfl_up_sync(0xffffffffu, a,  1);
    const float bp = __shfl_up_sync(0xffffffffu, b,  1);
    const float cp = __shfl_up_sync(0xffffffffu, cc, 1);
    float o = (lane == 0) ? o0 : fminf(fmaf(ap, o0, bp), cp);

    // 4) emit: batch 4 steps into float4, STS.128
    float* const so = &s_o[w][lane * OPITCH];
#pragma unroll
    for (int j4 = 0; j4 < SLEN / 4; ++j4) {
        float4 ov;
        {   const float A = ((mask >> (4*j4+0)) & 1u) ? A1 : A0;
            ov.x = o;  o = fminf(fmaf(A, o, Bc), OMAX); }
        {   const float A = ((mask >> (4*j4+1)) & 1u) ? A1 : A0;
            ov.y = o;  o = fminf(fmaf(A, o, Bc), OMAX); }
        {   const float A = ((mask >> (4*j4+2)) & 1u) ? A1 : A0;
            ov.z = o;  o = fminf(fmaf(A, o, Bc), OMAX); }
        {   const float A = ((mask >> (4*j4+3)) & 1u) ? A1 : A0;
            ov.w = o;  o = fminf(fmaf(A, o, Bc), OMAX); }
        *reinterpret_cast<float4*>(so + 4 * j4) = ov;
    }
    __syncwarp();

    // 5) drain: LDS.128 + rcp x4 + 2x STG.128 per group
    float* const outc = out + (size_t)row * T_LEN;
    float* const outl = out + (size_t)NUM_B * T_LEN + (size_t)row * T_LEN;
    const int sgl = lane >> 3;
    const int k4  = (lane & 7) * 4;
#pragma unroll
    for (int dd = 0; dd < 8; ++dd) {
        const int seg = dd * 4 + sgl;
        const float4 ov = *reinterpret_cast<const float4*>(&s_o[w][seg * OPITCH + k4]);
        float4 lv, cv;
        float inv;
        asm("rcp.approx.ftz.f32 %0, %1;" : "=f"(inv) : "f"(1.0f + ov.x));
        lv.x = ov.x * inv;  cv.x = fmaf(ov.x, s1, gg) * inv;
        asm("rcp.approx.ftz.f32 %0, %1;" : "=f"(inv) : "f"(1.0f + ov.y));
        lv.y = ov.y * inv;  cv.y = fmaf(ov.y, s1, gg) * inv;
        asm("rcp.approx.ftz.f32 %0, %1;" : "=f"(inv) : "f"(1.0f + ov.z));
        lv.z = ov.z * inv;  cv.z = fmaf(ov.z, s1, gg) * inv;
        asm("rcp.approx.ftz.f32 %0, %1;" : "=f"(inv) : "f"(1.0f + ov.w));
        lv.w = ov.w * inv;  cv.w = fmaf(ov.w, s1, gg) * inv;
        *reinterpret_cast<float4*>(outc + seg * SLEN + k4) = cv;
        *reinterpret_cast<float4*>(outl + seg * SLEN + k4) = lv;
    }
}

// ---------------------------------------------------------------------------
extern "C" void kernel_launch(void* const* d_in, const int* in_sizes, int n_in,
                              void* d_out, int out_size)
{
    const int*   X     = (const int*)  d_in[0];
    const int*   y     = (const int*)  d_in[1];
    const float* embed = (const float*)d_in[2];
    const float* W0    = (const float*)d_in[3];
    const float* b0    = (const float*)d_in[4];
    const float* W1    = (const float*)d_in[5];
    const float* b1    = (const float*)d_in[6];
    const float* Wout  = (const float*)d_in[7];
    const float* bout  = (const float*)d_in[8];

    mlp_kernel<<<NUM_B / MROWS, 256>>>(X, embed, W0, b0, W1, b1, Wout, bout);
    bkt_kernel<<<NUM_B / BWARPS, 32 * BWARPS>>>(y, (float*)d_out);
}